// round 1
// baseline (speedup 1.0000x reference)
#include <cuda_runtime.h>
#include <math.h>

// Problem constants (shapes are fixed by the dataset)
#define VOCAB   1000000
#define DIM     128
#define BATCH   4096
#define WINDOW  5
#define NEG     5
#define LMAX    4
#define NROWS   (BATCH * 2 * WINDOW)   // 40960

// log_sigmoid(x) = min(x,0) - log1p(exp(-|x|)), numerically stable
__device__ __forceinline__ float log_sigmoid(float x) {
    return fminf(x, 0.0f) - log1pf(__expf(-fabsf(x)));
}

// Ragged bag mean for one table row-set. lane owns floats [lane*4, lane*4+4).
// Predicated loads: up to LMAX independent 512B gathers in flight per bag.
__device__ __forceinline__ float4 bag_mean(const float* __restrict__ table,
                                           const int* __restrict__ idx_row,
                                           int len, int lane) {
    float4 acc = make_float4(0.f, 0.f, 0.f, 0.f);
    #pragma unroll
    for (int l = 0; l < LMAX; ++l) {
        if (l < len) {
            const float4 v = __ldg(reinterpret_cast<const float4*>(
                table + (size_t)idx_row[l] * DIM + lane * 4));
            acc.x += v.x; acc.y += v.y; acc.z += v.z; acc.w += v.w;
        }
    }
    float inv = 1.0f / (float)len;
    acc.x *= inv; acc.y *= inv; acc.z *= inv; acc.w *= inv;
    return acc;
}

__device__ __forceinline__ float dot4(float4 a, float4 b) {
    return a.x * b.x + a.y * b.y + a.z * b.z + a.w * b.w;
}

__device__ __forceinline__ float warp_sum(float v) {
    #pragma unroll
    for (int off = 16; off > 0; off >>= 1)
        v += __shfl_xor_sync(0xFFFFFFFFu, v, off);
    return v;
}

__global__ void zero_out_kernel(float* out) { out[0] = 0.0f; }

__global__ void __launch_bounds__(256)
skipgram_kernel(const float* __restrict__ u_table,
                const float* __restrict__ v_table,
                const int*   __restrict__ pos_u_idx,
                const int*   __restrict__ pos_u_len,
                const int*   __restrict__ pos_v_idx,
                const int*   __restrict__ pos_v_len,
                const int*   __restrict__ neg_v_idx,
                const int*   __restrict__ neg_v_len,
                float* __restrict__ out) {
    const int tid   = blockIdx.x * blockDim.x + threadIdx.x;
    const int warp  = tid >> 5;              // row n; grid sized exactly to NROWS warps
    const int lane  = threadIdx.x & 31;
    const int wslot = threadIdx.x >> 5;      // warp index within block (0..7)

    __shared__ float s_partial[8];

    // ---- embed_u = bag_mean(u_table, pos_u) ----
    const int u_len = __ldg(&pos_u_len[warp]);
    float4 eu = bag_mean(u_table, pos_u_idx + (size_t)warp * LMAX, u_len, lane);

    // ---- embed_v = bag_mean(v_table, pos_v) ----
    const int v_len = __ldg(&pos_v_len[warp]);
    float4 ev = bag_mean(v_table, pos_v_idx + (size_t)warp * LMAX, v_len, lane);

    // score = dot(embed_u, embed_v)
    float score = warp_sum(dot4(eu, ev));
    float loss  = log_sigmoid(score);

    // ---- negatives: 5 bags per row ----
    #pragma unroll
    for (int k = 0; k < NEG; ++k) {
        const size_t nrow = (size_t)warp * NEG + k;
        const int nlen = __ldg(&neg_v_len[nrow]);
        float4 nv = bag_mean(v_table, neg_v_idx + nrow * LMAX, nlen, lane);
        float ns = warp_sum(dot4(nv, eu));
        loss += log_sigmoid(-ns);
    }

    // per-row contribution to final scalar: -loss / BATCH
    if (lane == 0) s_partial[wslot] = -loss * (1.0f / (float)BATCH);
    __syncthreads();

    // block reduce (8 warps) then one atomic per block
    if (threadIdx.x == 0) {
        float bsum = 0.f;
        #pragma unroll
        for (int i = 0; i < 8; ++i) bsum += s_partial[i];
        atomicAdd(out, bsum);
    }
}

extern "C" void kernel_launch(void* const* d_in, const int* in_sizes, int n_in,
                              void* d_out, int out_size) {
    const float* u_table   = (const float*)d_in[0];
    const float* v_table   = (const float*)d_in[1];
    const int*   pos_u_idx = (const int*)d_in[2];
    const int*   pos_u_len = (const int*)d_in[3];
    const int*   pos_v_idx = (const int*)d_in[4];
    const int*   pos_v_len = (const int*)d_in[5];
    const int*   neg_v_idx = (const int*)d_in[6];
    const int*   neg_v_len = (const int*)d_in[7];
    float* out = (float*)d_out;

    zero_out_kernel<<<1, 1>>>(out);
    // 40960 warps / 8 warps per block = 5120 blocks, exact
    skipgram_kernel<<<NROWS / 8, 256>>>(u_table, v_table,
                                        pos_u_idx, pos_u_len,
                                        pos_v_idx, pos_v_len,
                                        neg_v_idx, neg_v_len, out);
}